// round 17
// baseline (speedup 1.0000x reference)
#include <cuda_runtime.h>
#include <cuda_bf16.h>
#include <math.h>
#include <stdint.h>

#define NB 128
#define NT 32
#define NIN 512
#define NH 512
#define NM 16
#define NWC 20
#define NR 4
#define NRW 80
#define NNIN 592
#define NIF 163
#define NIFP 192
#define CLIPV 20.0f
#define EPSF 1e-6f
#define DELTAF 5e-6f

#define NBLKS 148
#define NW (NBLKS * 8)   // 1184 warps

// ---------------- persistent state (device globals; allocation-free) ----------
__device__ float g_h[2][2][2][NB][NH];   // [parity][layer][cell][b][h]
__device__ float g_c[2][2][NB][NH];      // [layer][cell][b][h]
__device__ float g_inp[NB][NNIN];        // concat(out, read_vecs)
__device__ float g_ifc[NB][NIFP];        // iface projection result
__device__ float g_xpart[NT * 2048 * NB];// precomputed x@Wih partial, [t][n'][b]
__device__ float g_mem[2][NB][NM][NWC];
__device__ float g_link[2][NB][NM][NM];
__device__ float g_prec[2][NB][NM];
__device__ float g_rw[2][NB][NR][NM];
__device__ float g_ww[2][NB][NM];
__device__ float g_usage[2][NB][NM];
__device__ unsigned g_barCnt;

// ---------------- converted (bf16 hi/lo split, fragment-swizzled) weights ----
__device__ unsigned g_W00[128 * 64 * 256];   // l0 cell0: 2048 x (512x + 512h)
__device__ unsigned g_W01[128 * 69 * 256];   // l1 cell0: 2048 x 1104
__device__ unsigned g_W10[128 * 64 * 256];   // l0 cell1
__device__ unsigned g_W11[128 * 64 * 256];   // l1 cell1
__device__ unsigned g_Wif[2 * 12 * 32 * 256];// iface: 192(pad) x 512, per layer
__device__ unsigned g_Wo[32 * 37 * 256];     // out: 512 x 592
__device__ float g_bc[2 * 2 * 2048];         // gate-reordered biases [l][cell][n']

__device__ __forceinline__ float sigf(float x) { return 1.f / (1.f + expf(-x)); }
__device__ __forceinline__ float softplusf(float x) {
    return fmaxf(x, 0.f) + log1pf(expf(-fabsf(x)));
}
__device__ __forceinline__ float clipf(float x) {
    return fminf(fmaxf(x, -CLIPV), CLIPV);
}
__device__ __forceinline__ uint32_t packbf(float a, float b) {
    uint32_t r;
    asm("cvt.rn.bf16x2.f32 %0, %1, %2;" : "=r"(r) : "f"(b), "f"(a));
    return r;
}
__device__ __forceinline__ float bfhi(float x) {
    return __bfloat162float(__float2bfloat16_rn(x));
}
__device__ __forceinline__ void cvt_hilo(float x, float y, uint32_t& hi, uint32_t& lo) {
    uint32_t h = packbf(x, y);
    float hx = __uint_as_float(h << 16);
    float hy = __uint_as_float(h & 0xffff0000u);
    lo = packbf(x - hx, y - hy);
    hi = h;
}

// ---------------- init: zero all state --------------------------------------
__global__ void initk() {
    long i0 = blockIdx.x * (long)blockDim.x + threadIdx.x;
    long st = (long)gridDim.x * blockDim.x;
    if (i0 == 0) g_barCnt = 0u;
    for (long i = i0; i < 2L * 2 * 2 * NB * NH; i += st) ((float*)g_h)[i] = 0.f;
    for (long i = i0; i < 2L * 2 * NB * NH; i += st) ((float*)g_c)[i] = 0.f;
    for (long i = i0; i < (long)NB * NNIN; i += st) ((float*)g_inp)[i] = 0.f;
    for (long i = i0; i < 2L * NB * NM * NWC; i += st) ((float*)g_mem)[i] = 0.f;
    for (long i = i0; i < 2L * NB * NM * NM; i += st) ((float*)g_link)[i] = 0.f;
    for (long i = i0; i < 2L * NB * NM; i += st) {
        ((float*)g_prec)[i] = 0.f;
        ((float*)g_ww)[i] = 0.f;
        ((float*)g_usage)[i] = 0.f;
    }
    for (long i = i0; i < 2L * NB * NR * NM; i += st) ((float*)g_rw)[i] = 0.f;
}

// ---------------- fused weight conversion pre-pass (7 jobs, bf16 hi/lo) ------
__global__ void prepAll(
    const float* __restrict__ W_ih0, const float* __restrict__ W_hh0,
    const float* __restrict__ W_ih1, const float* __restrict__ W_hh1,
    const float* __restrict__ W_if,  const float* __restrict__ W_out,
    unsigned* pW00, unsigned* pW01, unsigned* pW10, unsigned* pW11,
    unsigned* pWif, unsigned* pWo)
{
    const float *W1, *W2;
    int ld1, K1, ld2, K2, gr, nReal, nPad;
    unsigned* dst;
    switch (blockIdx.y) {
        case 0: W1 = W_ih0; ld1 = NNIN; K1 = 512; W2 = W_hh0; ld2 = NH; K2 = 512;
                dst = pW00; gr = 1; nReal = 2048; nPad = 2048; break;
        case 1: W1 = W_ih0 + (size_t)4 * NH * NNIN; ld1 = NNIN; K1 = 592;
                W2 = W_hh0 + (size_t)4 * NH * NH; ld2 = NH; K2 = 512;
                dst = pW01; gr = 1; nReal = 2048; nPad = 2048; break;
        case 2: W1 = W_ih1; ld1 = NH; K1 = 512; W2 = W_hh1; ld2 = NH; K2 = 512;
                dst = pW10; gr = 1; nReal = 2048; nPad = 2048; break;
        case 3: W1 = W_ih1 + (size_t)4 * NH * NH; ld1 = NH; K1 = 512;
                W2 = W_hh1 + (size_t)4 * NH * NH; ld2 = NH; K2 = 512;
                dst = pW11; gr = 1; nReal = 2048; nPad = 2048; break;
        case 4: W1 = W_if; ld1 = NH; K1 = 512; W2 = W_if; ld2 = NH; K2 = 0;
                dst = pWif; gr = 0; nReal = NIF; nPad = 192; break;
        case 5: W1 = W_if + (size_t)NIF * NH; ld1 = NH; K1 = 512;
                W2 = W1; ld2 = NH; K2 = 0;
                dst = pWif + (size_t)12 * 32 * 256; gr = 0; nReal = NIF; nPad = 192; break;
        default: W1 = W_out; ld1 = NNIN; K1 = 592; W2 = W_out; ld2 = NNIN; K2 = 0;
                dst = pWo; gr = 0; nReal = 512; nPad = 512; break;
    }
    const int K16 = (K1 + K2) >> 4;
    int idx = blockIdx.x * blockDim.x + threadIdx.x;
    int total = (nPad >> 4) * K16 * 32;
    if (idx >= total) return;
    int lane = idx & 31;
    int k16 = (idx >> 5) % K16;
    int nfrag = (idx >> 5) / K16;
    int r0 = lane >> 2, c0 = lane & 3;
    uint4 hi, lo;
    unsigned* ph = (unsigned*)&hi;
    unsigned* pl = (unsigned*)&lo;
#pragma unroll
    for (int reg = 0; reg < 4; ++reg) {
        int r = nfrag * 16 + r0 + 8 * (reg & 1);
        int kb = k16 * 16 + 2 * c0 + 8 * (reg >> 1);
        int row;
        if (gr) { int j = r >> 2, g = r & 3; row = g * NH + j; }
        else row = r;
        float x0 = 0.f, x1 = 0.f;
        if (row < nReal) {
            x0 = (kb < K1) ? W1[(size_t)row * ld1 + kb]
                           : W2[(size_t)row * ld2 + (kb - K1)];
            x1 = (kb + 1 < K1) ? W1[(size_t)row * ld1 + kb + 1]
                               : W2[(size_t)row * ld2 + (kb + 1 - K1)];
        }
        float h0 = bfhi(x0), h1 = bfhi(x1);
        ph[reg] = packbf(h0, h1);
        pl[reg] = packbf(x0 - h0, x1 - h1);
    }
    ((uint4*)dst)[((size_t)(nfrag * K16 + k16) * 2 + 0) * 32 + lane] = hi;
    ((uint4*)dst)[((size_t)(nfrag * K16 + k16) * 2 + 1) * 32 + lane] = lo;
}

__global__ void prepbias(const float* bih0, const float* bhh0,
                         const float* bih1, const float* bhh1, float* bc)
{
    int i = blockIdx.x * blockDim.x + threadIdx.x;
    if (i >= 2 * 2 * 2048) return;
    int n = i & 2047;
    int cell = (i >> 11) & 1;
    int l = i >> 12;
    int j = n >> 2, g = n & 3;
    const float* bi = cell ? bih1 : bih0;
    const float* bh = cell ? bhh1 : bhh0;
    bc[i] = bi[(size_t)l * 4 * NH + g * NH + j] + bh[(size_t)l * 4 * NH + g * NH + j];
}

// ---------------- compensated bf16 MMA core ----------------------------------
__device__ __forceinline__ void mma_bf16(float c[4], uint4 a, uint32_t b0, uint32_t b1) {
    asm volatile(
        "mma.sync.aligned.m16n8k16.row.col.f32.bf16.bf16.f32 "
        "{%0,%1,%2,%3}, {%4,%5,%6,%7}, {%8,%9}, {%0,%1,%2,%3};"
        : "+f"(c[0]), "+f"(c[1]), "+f"(c[2]), "+f"(c[3])
        : "r"(a.x), "r"(a.y), "r"(a.z), "r"(a.w), "r"(b0), "r"(b1));
}

// warp GEMM: 16 n' x 16 batch (B rows bc0 and bc0+8 share each W load).
// B loads via __ldcg (L2-coherent: cross-SM data within the persistent launch).
__device__ __forceinline__ void gemm2p(
    const float* __restrict__ A1, int sA1, int K1,
    const float* __restrict__ A2, int sA2,
    int nch, const uint4* __restrict__ Wp,
    int lane, int bc0, float accA[4], float accB[4])
{
    const int kb = 2 * (lane & 3);
    const float* a1A = A1 + (size_t)bc0 * sA1;
    const float* a2A = A2 + (size_t)bc0 * sA2 - K1;
    const float* a1B = A1 + (size_t)(bc0 + 8) * sA1;
    const float* a2B = A2 + (size_t)(bc0 + 8) * sA2 - K1;
    accA[0] = accA[1] = accA[2] = accA[3] = 0.f;
    accB[0] = accB[1] = accB[2] = accB[3] = 0.f;
    float2 BA0[2], BA1[2], BB0[2], BB1[2];
    uint4 WH[2], WL[2];

    auto ld = [&](int ch, int s) {
        int k = ch * 16 + kb;
        const float* pa = (k < K1) ? a1A : a2A;
        const float* pb = (k < K1) ? a1B : a2B;
        BA0[s] = __ldcg((const float2*)(pa + k));
        BA1[s] = __ldcg((const float2*)(pa + k + 8));
        BB0[s] = __ldcg((const float2*)(pb + k));
        BB1[s] = __ldcg((const float2*)(pb + k + 8));
    };

    ld(0, 0);
    WH[0] = Wp[0];
    WL[0] = Wp[32];
    if (nch > 1) {
        ld(1, 1);
        WH[1] = Wp[64];
        WL[1] = Wp[96];
    }
    for (int ch = 0; ch < nch; ++ch) {
        const int s = ch & 1;
        uint32_t ah0, al0, ah1, al1, bh0, bl0, bh1, bl1;
        cvt_hilo(BA0[s].x, BA0[s].y, ah0, al0);
        cvt_hilo(BA1[s].x, BA1[s].y, ah1, al1);
        cvt_hilo(BB0[s].x, BB0[s].y, bh0, bl0);
        cvt_hilo(BB1[s].x, BB1[s].y, bh1, bl1);
        mma_bf16(accA, WH[s], ah0, ah1);
        mma_bf16(accA, WL[s], ah0, ah1);
        mma_bf16(accA, WH[s], al0, al1);
        mma_bf16(accB, WH[s], bh0, bh1);
        mma_bf16(accB, WL[s], bh0, bh1);
        mma_bf16(accB, WH[s], bl0, bl1);
        if (ch + 2 < nch) {
            ld(ch + 2, s);
            WH[s] = Wp[(size_t)(ch + 2) * 64];
            WL[s] = Wp[(size_t)(ch + 2) * 64 + 32];
        }
    }
}

// cell job: 16 n' (1 nfrag = 4 gate quads) x 16 batch; LSTM epilogue
// jobs: nfrag = job>>3 (0..127), tb = job&7 (16-batch tiles)
__device__ __forceinline__ void cellJob2(
    int job, int lane, float* slab,
    const float* A1, int sA1, int K1, const float* A2, int sA2,
    int nch, const unsigned* W, int kstr, int chOff,
    const float* bias, float* cio, float* hout, float* clipOut,
    const float* extra)
{
    const int CP = 17;
    int nfrag = job >> 3, tb = job & 7;
    int bc0 = tb * 16 + (lane >> 2);
    const uint4* Wp = (const uint4*)W + ((size_t)nfrag * kstr + chOff) * 64 + lane;
    float accA[4], accB[4];
    gemm2p(A1, sA1, K1, A2, sA2, nch, Wp, lane, bc0, accA, accB);
    int r = lane >> 2, cc = 2 * (lane & 3);
    slab[r * CP + cc] = accA[0];
    slab[r * CP + cc + 1] = accA[1];
    slab[(r + 8) * CP + cc] = accA[2];
    slab[(r + 8) * CP + cc + 1] = accA[3];
    slab[r * CP + 8 + cc] = accB[0];
    slab[r * CP + 8 + cc + 1] = accB[1];
    slab[(r + 8) * CP + 8 + cc] = accB[2];
    slab[(r + 8) * CP + 8 + cc + 1] = accB[3];
    __syncwarp();
#pragma unroll
    for (int it = 0; it < 2; ++it) {
        int idx = it * 32 + lane;
        int j = idx & 3, bl = idx >> 2;     // j 0..3, bl 0..15
        int b = tb * 16 + bl;
        int jg = nfrag * 4 + j;
        int nb = nfrag * 16 + j * 4;
        float e0 = 0.f, e1 = 0.f, e2 = 0.f, e3 = 0.f;
        if (extra) {
            const float* ep = extra + (size_t)nb * NB + b;
            e0 = ep[0]; e1 = ep[NB]; e2 = ep[2 * NB]; e3 = ep[3 * NB];
        }
        float gi = slab[(j * 4 + 0) * CP + bl] + bias[nb + 0] + e0;
        float gf = slab[(j * 4 + 1) * CP + bl] + bias[nb + 1] + e1;
        float gg = slab[(j * 4 + 2) * CP + bl] + bias[nb + 2] + e2;
        float go = slab[(j * 4 + 3) * CP + bl] + bias[nb + 3] + e3;
        float cold = cio[(size_t)b * NH + jg];
        float cn = sigf(gf) * cold + sigf(gi) * tanhf(gg);
        float hn = sigf(go) * tanhf(cn);
        cio[(size_t)b * NH + jg] = cn;
        hout[(size_t)b * NH + jg] = hn;
        if (clipOut) clipOut[(size_t)b * NNIN + jg] = clipf(hn);
    }
    __syncwarp();
}

// linear job: 16 n x 16 batch, bias + row guard (iface / outproj)
__device__ __forceinline__ void linJob2(
    int job, int lane, float* slab,
    const float* A, int sA, int K1full, int nch,
    const unsigned* W, int kstr,
    const float* bias, int nReal, float* out, int rowStride)
{
    const int CP = 17;
    int nfrag = job >> 3, tb = job & 7;
    int bc0 = tb * 16 + (lane >> 2);
    const uint4* Wp = (const uint4*)W + (size_t)nfrag * kstr * 64 + lane;
    float accA[4], accB[4];
    gemm2p(A, sA, K1full, A, sA, nch, Wp, lane, bc0, accA, accB);
    int r = lane >> 2, cc = 2 * (lane & 3);
    slab[r * CP + cc] = accA[0];
    slab[r * CP + cc + 1] = accA[1];
    slab[(r + 8) * CP + cc] = accA[2];
    slab[(r + 8) * CP + cc + 1] = accA[3];
    slab[r * CP + 8 + cc] = accB[0];
    slab[r * CP + 8 + cc + 1] = accB[1];
    slab[(r + 8) * CP + 8 + cc] = accB[2];
    slab[(r + 8) * CP + 8 + cc + 1] = accB[3];
    __syncwarp();
#pragma unroll
    for (int it = 0; it < 8; ++it) {
        int idx = it * 32 + lane;
        int n = idx & 15, bl = idx >> 4;    // n 0..15, bl 0..15
        int ng = nfrag * 16 + n;
        if (ng < nReal)
            out[(size_t)(tb * 16 + bl) * rowStride + ng] = slab[n * CP + bl] + bias[ng];
    }
    __syncwarp();
}

// ---------------- warp-level DNC memory step (R11-proven) ---------------------
__device__ void memstepWarp(int lane, int b,
    const float* ifcg, float* memg, float* linkg, float* precg,
    float* rwg, float* wwg, float* usg, float* inp, float* ws)
{
    const int RS = 80, WK = 84, WS = 104, ER = 105, WV = 125,
              FG = 145, AG = 149, WG = 150, RM = 151;
    float* ifc = ws;
    float* sm  = ws + 164;
    float* sl  = ws + 484;
    float* sp  = ws + 740;
    float* srw = ws + 756;
    float* sww = ws + 820;
    float* sus = ws + 836;
    float* wcw = ws + 852;
    float* alo = ws + 868;
    float* rcw = ws + 884;
    float* fwd = ws + 948;
    float* bwd = ws + 1012;

    for (int i = lane; i < NIF; i += 32) ifc[i] = __ldcg(ifcg + (size_t)b * NIFP + i);
    for (int i = lane; i < 320; i += 32) sm[i] = memg[b * 320 + i];
    for (int i = lane; i < 256; i += 32) sl[i] = linkg[b * 256 + i];
    if (lane < 16) {
        sp[lane] = precg[b * 16 + lane];
        sww[lane] = wwg[b * 16 + lane];
        sus[lane] = usg[b * 16 + lane];
    }
    for (int i = lane; i < 64; i += 32) srw[i] = rwg[b * 64 + i];
    __syncwarp();

    if (lane < 16) {
        float uu = sus[lane] + (1.f - sus[lane]) * sww[lane];
        float psi = 1.f;
#pragma unroll
        for (int r = 0; r < NR; ++r) psi *= 1.f - sigf(ifc[FG + r]) * srw[r * 16 + lane];
        sus[lane] = uu * psi;
        float kn2 = 0.f, dot = 0.f, mn2 = 0.f;
#pragma unroll
        for (int w = 0; w < NWC; ++w) {
            float kv = tanhf(ifc[WK + w]);
            float mv = sm[lane * NWC + w];
            kn2 = fmaf(kv, kv, kn2);
            mn2 = fmaf(mv, mv, mn2);
            dot = fmaf(kv, mv, dot);
        }
        float v = dot / ((sqrtf(kn2) + EPSF) * (sqrtf(mn2) + EPSF));
        v *= softplusf(ifc[WS]);
        float mx = v;
#pragma unroll
        for (int o = 8; o; o >>= 1) mx = fmaxf(mx, __shfl_xor_sync(0xffffu, mx, o, 16));
        float e = expf(v - mx);
        float s = e;
#pragma unroll
        for (int o = 8; o; o >>= 1) s += __shfl_xor_sync(0xffffu, s, o, 16);
        wcw[lane] = e / s;
    }
    __syncwarp();
    if (lane == 0) {
        float u[16]; int idx[16];
        for (int m = 0; m < 16; ++m) { u[m] = DELTAF + (1.f - DELTAF) * sus[m]; idx[m] = m; }
        for (int i = 1; i < 16; ++i) {
            float kv = u[i]; int ki = idx[i]; int j = i;
            while (j > 0 && u[j - 1] > kv) { u[j] = u[j - 1]; idx[j] = idx[j - 1]; --j; }
            u[j] = kv; idx[j] = ki;
        }
        float prod = 1.f;
        for (int j = 0; j < 16; ++j) { alo[idx[j]] = (1.f - u[j]) * prod; prod *= u[j]; }
    }
    __syncwarp();
    if (lane < 16) {
        float ag = sigf(ifc[AG]), wg = sigf(ifc[WG]);
        sww[lane] = wg * (ag * alo[lane] + (1.f - ag) * wcw[lane]);
    }
    __syncwarp();
    for (int i = lane; i < 320; i += 32) {
        int m = i / NWC, w = i % NWC;
        float e = sigf(ifc[ER + w]);
        float v = tanhf(ifc[WV + w]);
        sm[i] = sm[i] * (1.f - sww[m] * e) + sww[m] * v;
    }
    __syncwarp();
    for (int i = lane; i < 256; i += 32) {
        int ii = i >> 4, jj = i & 15;
        sl[i] = (ii == jj) ? 0.f
                           : (1.f - sww[ii] - sww[jj]) * sl[i] + sww[ii] * sp[jj];
    }
    __syncwarp();
    if (lane < 16) {
        float s = 0.f;
#pragma unroll
        for (int m = 0; m < 16; ++m) s += sww[m];
        sp[lane] = (1.f - s) * sp[lane] + sww[lane];
    }
    __syncwarp();
#pragma unroll
    for (int it = 0; it < 2; ++it) {
        int i = it * 32 + lane;
        int r = i >> 4, m = i & 15;
        float kn2 = 0.f, dot = 0.f, mn2 = 0.f;
#pragma unroll
        for (int w = 0; w < NWC; ++w) {
            float kv = tanhf(ifc[r * NWC + w]);
            float mv = sm[m * NWC + w];
            kn2 = fmaf(kv, kv, kn2);
            mn2 = fmaf(mv, mv, mn2);
            dot = fmaf(kv, mv, dot);
        }
        float v = dot / ((sqrtf(kn2) + EPSF) * (sqrtf(mn2) + EPSF));
        v *= softplusf(ifc[RS + r]);
        float mx = v;
#pragma unroll
        for (int o = 8; o; o >>= 1) mx = fmaxf(mx, __shfl_xor_sync(0xffffffffu, mx, o, 16));
        float e = expf(v - mx);
        float s = e;
#pragma unroll
        for (int o = 8; o; o >>= 1) s += __shfl_xor_sync(0xffffffffu, s, o, 16);
        rcw[i] = e / s;
    }
    __syncwarp();
#pragma unroll
    for (int it = 0; it < 2; ++it) {
        int i = it * 32 + lane;
        int r = i >> 4, q = i & 15;
        float f = 0.f, bb = 0.f;
#pragma unroll
        for (int j = 0; j < 16; ++j) {
            f = fmaf(sl[q * 16 + j], srw[r * 16 + j], f);
            bb = fmaf(srw[r * 16 + j], sl[j * 16 + q], bb);
        }
        fwd[i] = f;
        bwd[i] = bb;
    }
    __syncwarp();
#pragma unroll
    for (int it = 0; it < 2; ++it) {
        int i = it * 32 + lane;
        int r = i >> 4;
        float e0 = ifc[RM + r * 3 + 0], e1 = ifc[RM + r * 3 + 1], e2 = ifc[RM + r * 3 + 2];
        float mx = fmaxf(e0, fmaxf(e1, e2));
        float x0 = expf(e0 - mx), x1 = expf(e1 - mx), x2 = expf(e2 - mx);
        float inv = 1.f / (x0 + x1 + x2);
        srw[i] = (x0 * bwd[i] + x1 * fwd[i] + x2 * rcw[i]) * inv;
    }
    __syncwarp();
    for (int i = lane; i < NRW; i += 32) {
        int r = i / NWC, w = i % NWC;
        float s = 0.f;
#pragma unroll
        for (int m = 0; m < 16; ++m) s = fmaf(srw[r * 16 + m], sm[m * NWC + w], s);
        inp[(size_t)b * NNIN + NIN + i] = s;
    }
    for (int i = lane; i < 320; i += 32) memg[b * 320 + i] = sm[i];
    for (int i = lane; i < 256; i += 32) linkg[b * 256 + i] = sl[i];
    if (lane < 16) {
        precg[b * 16 + lane] = sp[lane];
        wwg[b * 16 + lane] = sww[lane];
        usg[b * 16 + lane] = sus[lane];
    }
    for (int i = lane; i < 64; i += 32) rwg[b * 64 + i] = srw[i];
    __syncwarp();
}

// ---------------- software grid barrier (R11-verbatim, both fences) -----------
__device__ __forceinline__ void gbar(unsigned& target) {
    __threadfence();
    __syncthreads();
    if (threadIdx.x == 0) {
        atomicAdd(&g_barCnt, 1u);
        while (atomicAdd(&g_barCnt, 0u) < target) { }
        __threadfence();
    }
    __syncthreads();
    target += NBLKS;
}

// ---------------- the fused persistent recurrence kernel ---------------------
__global__ __launch_bounds__(256) void fused(
    const float* __restrict__ b_if, const float* __restrict__ b_out,
    float* __restrict__ y)
{
    __shared__ float sh[8 * 1088];
    const int wid = blockIdx.x * 8 + (threadIdx.x >> 5);
    const int lane = threadIdx.x & 31;
    float* slab = sh + (threadIdx.x >> 5) * 1088;
    float* pinp = &g_inp[0][0];
    unsigned target = NBLKS;

    for (int t = 0; t < NT; ++t) {
        const int p = t & 1;
        // S1: cell0-l0 (1024 jobs) + outproj of t-1 (256 jobs)
        for (int job = wid; job < 1280; job += NW) {
            if (job < 1024)
                cellJob2(job, lane, slab,
                         &g_h[p][0][0][0][0], NH, 512, &g_h[p][0][0][0][0], NH,
                         32, g_W00, 64, 32,
                         g_bc, &g_c[0][0][0][0], &g_h[p ^ 1][0][0][0][0], nullptr,
                         g_xpart + (size_t)t * 2048 * NB);
            else if (t > 0)
                linJob2(job - 1024, lane, slab,
                        pinp, NNIN, 592, 37, g_Wo, 37,
                        b_out, 512, y + (size_t)(t - 1) * NIN, NT * NIN);
        }
        gbar(target);
        // S2: cell1-l0
        for (int job = wid; job < 1024; job += NW)
            cellJob2(job, lane, slab,
                     &g_h[p ^ 1][0][0][0][0], NH, 512, &g_h[p][0][1][0][0], NH,
                     64, g_W10, 64, 0,
                     g_bc + 2048, &g_c[0][1][0][0], &g_h[p ^ 1][0][1][0][0], pinp,
                     nullptr);
        gbar(target);
        // S3: iface l0 (96 jobs)
        if (wid < 96)
            linJob2(wid, lane, slab,
                    pinp, NNIN, 512, 32, g_Wif, 32,
                    b_if, NIF, &g_ifc[0][0], NIFP);
        gbar(target);
        // S4: memstep l0
        if (wid < NB)
            memstepWarp(lane, wid, &g_ifc[0][0],
                        &g_mem[0][0][0][0], &g_link[0][0][0][0], &g_prec[0][0][0],
                        &g_rw[0][0][0][0], &g_ww[0][0][0], &g_usage[0][0][0],
                        pinp, slab);
        gbar(target);
        // S5: cell0-l1
        for (int job = wid; job < 1024; job += NW)
            cellJob2(job, lane, slab,
                     pinp, NNIN, 592, &g_h[p][1][0][0][0], NH,
                     69, g_W01, 69, 0,
                     g_bc + 2 * 2048, &g_c[1][0][0][0], &g_h[p ^ 1][1][0][0][0],
                     nullptr, nullptr);
        gbar(target);
        // S6: cell1-l1
        for (int job = wid; job < 1024; job += NW)
            cellJob2(job, lane, slab,
                     &g_h[p ^ 1][1][0][0][0], NH, 512, &g_h[p][1][1][0][0], NH,
                     64, g_W11, 64, 0,
                     g_bc + 3 * 2048, &g_c[1][1][0][0], &g_h[p ^ 1][1][1][0][0],
                     pinp, nullptr);
        gbar(target);
        // S7: iface l1
        if (wid < 96)
            linJob2(wid, lane, slab,
                    pinp, NNIN, 512, 32, g_Wif + 12 * 32 * 256, 32,
                    b_if + NIF, NIF, &g_ifc[0][0], NIFP);
        gbar(target);
        // S8: memstep l1
        if (wid < NB)
            memstepWarp(lane, wid, &g_ifc[0][0],
                        &g_mem[1][0][0][0], &g_link[1][0][0][0], &g_prec[1][0][0],
                        &g_rw[1][0][0][0], &g_ww[1][0][0], &g_usage[1][0][0],
                        pinp, slab);
        gbar(target);
    }
    // final output projection (t = NT-1)
    for (int job = wid; job < 256; job += NW)
        linJob2(job, lane, slab,
                pinp, NNIN, 592, 37, g_Wo, 37,
                b_out, 512, y + (size_t)(NT - 1) * NIN, NT * NIN);
}

// ---------------- x-precompute (one-time; R11-proven, 4x W reuse) -------------
__global__ __launch_bounds__(128) void xprep(
    const float* __restrict__ x, const unsigned* __restrict__ W,
    float* __restrict__ xpart)
{
    __shared__ float sbuf[4][16 * 9];
    const int lane = threadIdx.x & 31, warp = threadIdx.x >> 5;
    const int job = blockIdx.x * 4 + warp;
    const int nfrag = job & 127;
    const int tq = job >> 7;
    const uint4* Wp = (const uint4*)W + (size_t)nfrag * 64 * 64 + lane;
    const int kb = 2 * (lane & 3);
    const float* rA[4];
#pragma unroll
    for (int f = 0; f < 4; ++f)
        rA[f] = x + (size_t)(tq * 32 + f * 8 + (lane >> 2)) * NIN;
    float acc[4][4];
#pragma unroll
    for (int f = 0; f < 4; ++f)
        acc[f][0] = acc[f][1] = acc[f][2] = acc[f][3] = 0.f;
    for (int ch = 0; ch < 32; ++ch) {
        uint4 WH = Wp[(size_t)ch * 64];
        uint4 WL = Wp[(size_t)ch * 64 + 32];
        int k = ch * 16 + kb;
#pragma unroll
        for (int f = 0; f < 4; ++f) {
            float2 v0 = *(const float2*)(rA[f] + k);
            float2 v1 = *(const float2*)(rA[f] + k + 8);
            uint32_t bh0, bl0, bh1, bl1;
            cvt_hilo(v0.x, v0.y, bh0, bl0);
            cvt_hilo(v1.x, v1.y, bh1, bl1);
            mma_bf16(acc[f], WH, bh0, bh1);
            mma_bf16(acc[f], WL, bh0, bh1);
            mma_bf16(acc[f], WH, bl0, bl1);
        }
    }
    float* slab = sbuf[warp];
    int r = lane >> 2, cc = 2 * (lane & 3);
#pragma unroll
    for (int f = 0; f < 4; ++f) {
        __syncwarp();
        slab[r * 9 + cc] = acc[f][0];
        slab[r * 9 + cc + 1] = acc[f][1];
        slab[(r + 8) * 9 + cc] = acc[f][2];
        slab[(r + 8) * 9 + cc + 1] = acc[f][3];
        __syncwarp();
#pragma unroll
        for (int i = 0; i < 4; ++i) {
            int idx = i * 32 + lane;
            int n = idx >> 3, bl = idx & 7;
            int ng = nfrag * 16 + n;
            int bg = tq * 32 + f * 8 + bl;
            int t = bg & (NT - 1);
            int bi = bg >> 5;
            xpart[((size_t)t * 2048 + ng) * NB + bi] = slab[n * 9 + bl];
        }
    }
}

// ---------------- host driver ------------------------------------------------
extern "C" void kernel_launch(void* const* d_in, const int* in_sizes, int n_in,
                              void* d_out, int out_size)
{
    const float* x      = (const float*)d_in[0];
    const float* W_ih0  = (const float*)d_in[1];
    const float* W_hh0  = (const float*)d_in[2];
    const float* b_ih0  = (const float*)d_in[3];
    const float* b_hh0  = (const float*)d_in[4];
    const float* W_ih1  = (const float*)d_in[5];
    const float* W_hh1  = (const float*)d_in[6];
    const float* b_ih1  = (const float*)d_in[7];
    const float* b_hh1  = (const float*)d_in[8];
    const float* W_if   = (const float*)d_in[9];
    const float* b_if   = (const float*)d_in[10];
    const float* W_out  = (const float*)d_in[11];
    const float* b_out  = (const float*)d_in[12];
    float* y = (float*)d_out;

    float *pxp, *pbc;
    unsigned *pW00, *pW01, *pW10, *pW11, *pWif, *pWo;
    cudaGetSymbolAddress((void**)&pxp,  g_xpart);
    cudaGetSymbolAddress((void**)&pW00, g_W00);
    cudaGetSymbolAddress((void**)&pW01, g_W01);
    cudaGetSymbolAddress((void**)&pW10, g_W10);
    cudaGetSymbolAddress((void**)&pW11, g_W11);
    cudaGetSymbolAddress((void**)&pWif, g_Wif);
    cudaGetSymbolAddress((void**)&pWo,  g_Wo);
    cudaGetSymbolAddress((void**)&pbc,  g_bc);

    initk<<<512, 256>>>();
    prepAll<<<dim3(1104, 7), 256>>>(W_ih0, W_hh0, W_ih1, W_hh1, W_if,
                                    W_out, pW00, pW01, pW10, pW11, pWif, pWo);
    prepbias<<<(2 * 2 * 2048 + 255) / 256, 256>>>(b_ih0, b_hh0, b_ih1, b_hh1, pbc);
    xprep<<<4096, 128>>>(x, pW00, pxp);
    fused<<<NBLKS, 256>>>(b_if, b_out, y);
}